// round 7
// baseline (speedup 1.0000x reference)
#include <cuda_runtime.h>
#include <cuda_bf16.h>

// SEIR RNN, segment-parallel recompute (single kernel, no checkpoints).
//
// R1-R6 data: four structurally different kernels all pin at ~36us with
// DRAM 50%, L2 49%, L1 58%, occ ~20% -- nothing saturated.  Diagnosis:
// latency x MLP equilibrium at 14 warps/SM (grid-limited by 1 thread per
// 200-step sequential trajectory).  Fix: lane = (trajectory, segment);
// each lane recomputes 25*sg warmup steps (identical arithmetic -> identical
// bits) then emits its 25-step segment.  8x thread parallelism, small smem
// tiles -> ~40 warps/SM, 3x store MLP.

#define BATCH    65536
#define STEPS    200
#define SEGLEN   25
#define NSEG     8            // segments per trajectory
#define TRAJ_W   4            // trajectories per warp
#define TPB      128
#define WARPS    (TPB / 32)
#define TRAJ_BLK (WARPS * TRAJ_W)   // 16 trajectories per block
#define TSTRIDE  11           // tile row stride in float4 (176 B, conflict-free)

struct Coef { float kB, cA, cC, kA, kC; };

__device__ __forceinline__ void step(const Coef& c, float& s, float& e,
                                     float& i, float& r)
{
    float p     = e + i;
    float inflH = c.kB * p * s;
    float eo = e, io = i;
    s = s - inflH;
    e = fmaf(c.cA, eo, inflH);
    i = fmaf(c.cC, io, c.kA * eo);
    r = fmaf(c.kC, io, r);
}

__global__ __launch_bounds__(TPB)
void seir_kernel(const float4* __restrict__ init,
                 const float*  __restrict__ w,
                 float4*       __restrict__ out)
{
    __shared__ float4 tile[WARPS][32][TSTRIDE];

    const int tid  = threadIdx.x;
    const int wrp  = tid >> 5;
    const int lane = tid & 31;
    const int tl   = lane >> 3;          // trajectory within warp (0..3)
    const int sg   = lane & 7;           // segment (0..7)
    const int trajBase = blockIdx.x * TRAJ_BLK + wrp * TRAJ_W;

    Coef c;
    {
        const float A = w[4], B = w[5], C = w[6], H = 0.5f;
        c.kB = H * B * 1e-5f;            // H*B/N_POP
        c.cA = 1.0f - H * A;
        c.cC = 1.0f - H * C;
        c.kA = H * A;
        c.kC = H * C;
    }

    float4 x = init[trajBase + tl];
    float s = x.x, e = x.y, i = x.z, r = x.w;

    // ---- warmup: advance to this lane's segment start (identical bits) ----
    const int warm = SEGLEN * sg;
    #pragma unroll 1
    for (int t = 0; t < warm; ++t)
        step(c, s, e, i, r);

    // ---- emit 25 steps in rounds of 8,8,9; drain coalesced per round ----
    float4* const out_traj = out + (size_t)trajBase * STEPS;

    #pragma unroll
    for (int rnd = 0; rnd < 3; ++rnd) {
        const int cstart = rnd * 8;
        const int len    = (rnd == 2) ? 9 : 8;

        for (int tt = 0; tt < len; ++tt) {
            step(c, s, e, i, r);
            tile[wrp][lane][tt] = make_float4(s, e, i, r);
        }
        __syncwarp();

        // drain: iter m covers rows m*4..m*4+3 (8 lanes each) ->
        // 4 full 128B lines per STG.  row = tl*8+sg', step = lane&7.
        #pragma unroll
        for (int m = 0; m < 8; ++m) {
            int row = m * 4 + (lane >> 3);         // source lane / tile row
            int st  = lane & 7;                    // step within round
            int rtl = row >> 3;                    // trajectory
            int rsg = row & 7;                     // segment
            out_traj[(size_t)rtl * STEPS + rsg * SEGLEN + cstart + st] =
                tile[wrp][row][st];
        }
        if (len == 9) {
            // leftover step 24: one float4 per (traj, segment)
            out_traj[(size_t)(lane >> 3) * STEPS + (lane & 7) * SEGLEN + 24] =
                tile[wrp][lane][8];
        }
        __syncwarp();
    }
}

extern "C" void kernel_launch(void* const* d_in, const int* in_sizes, int n_in,
                              void* d_out, int out_size)
{
    const float4* init = (const float4*)d_in[0];   // (65536,1,4) f32
    const float*  wts  = (const float*)d_in[1];    // (7,) f32
    float4*       out  = (float4*)d_out;           // (65536,200,1,4) f32

    seir_kernel<<<BATCH / TRAJ_BLK, TPB>>>(init, wts, out);
}